// round 1
// baseline (speedup 1.0000x reference)
#include <cuda_runtime.h>
#include <math.h>
#include <stdint.h>

// Problem constants
#define NTOK 32768   // B*T = 4*8192
#define DDIM 512
#define NEXP 8
#define FDIM 2048
#define CAP  4096

// ---------------- device scratch (static; no allocations allowed) -----------
__device__ float g_logitsT[NEXP * NTOK];          // [E][N]
__device__ float g_colmax[NEXP];
__device__ float g_colsum[NEXP];
__device__ int   g_idx [NEXP * CAP];              // selected token indices
__device__ float g_vals[NEXP * CAP];              // softmax vals at selection
__device__ float g_h[(size_t)NEXP * CAP * FDIM];  // 256 MB intermediate h

// ---------------------------------------------------------------------------
__device__ __forceinline__ unsigned f2k(float f) {
    unsigned u = __float_as_uint(f);
    return u ^ ((u & 0x80000000u) ? 0xFFFFFFFFu : 0x80000000u); // order-preserving
}
__device__ __forceinline__ float gelu_exact(float v) {
    return 0.5f * v * (1.0f + erff(v * 0.70710678118654752440f));
}

// ---------------- K1: logits = x @ Wr, stored transposed [E][N] -------------
__global__ void k_logits(const float* __restrict__ x, const float* __restrict__ Wr)
{
    __shared__ float sW[NEXP * DDIM];  // transposed: [e][d], conflict-free reads
    int tid = threadIdx.x;
    for (int i = tid; i < NEXP * DDIM; i += 256) {
        int e = i >> 9, d = i & 511;
        sW[i] = Wr[d * NEXP + e];
    }
    __syncthreads();
    int warp = tid >> 5, lane = tid & 31;
    int t = blockIdx.x * 8 + warp;
    const float* xr = x + (size_t)t * DDIM;
    float acc[NEXP] = {};
#pragma unroll
    for (int i = 0; i < DDIM / 32; i++) {
        float xv = xr[lane + 32 * i];
#pragma unroll
        for (int e = 0; e < NEXP; e++)
            acc[e] += xv * sW[e * DDIM + lane + 32 * i];
    }
#pragma unroll
    for (int e = 0; e < NEXP; e++) {
#pragma unroll
        for (int o = 16; o > 0; o >>= 1)
            acc[e] += __shfl_xor_sync(0xffffffffu, acc[e], o);
    }
    if (lane == 0) {
#pragma unroll
        for (int e = 0; e < NEXP; e++)
            g_logitsT[e * NTOK + t] = acc[e];
    }
}

// ---------------- K2: per-expert column max + sum(exp) ----------------------
__global__ void k_colstats()
{
    int e = blockIdx.x;
    const float* col = g_logitsT + e * NTOK;
    __shared__ float red[512];
    int tid = threadIdx.x;
    float mx = -INFINITY;
    for (int n = tid; n < NTOK; n += 512) mx = fmaxf(mx, col[n]);
    red[tid] = mx; __syncthreads();
    for (int s = 256; s > 0; s >>= 1) {
        if (tid < s) red[tid] = fmaxf(red[tid], red[tid + s]);
        __syncthreads();
    }
    mx = red[0]; __syncthreads();
    float sm = 0.f;
    for (int n = tid; n < NTOK; n += 512) sm += expf(col[n] - mx);
    red[tid] = sm; __syncthreads();
    for (int s = 256; s > 0; s >>= 1) {
        if (tid < s) red[tid] += red[tid + s];
        __syncthreads();
    }
    if (tid == 0) { g_colmax[e] = mx; g_colsum[e] = red[0]; }
}

// ---------------- K3: per-expert exact top-CAP via radix select -------------
// 1 CTA per expert, 1024 threads. Exact threshold; ties taken lowest-index
// first (matches jax.lax.top_k selection set).
__global__ void k_select()
{
    int e = blockIdx.x;
    const float* col = g_logitsT + e * NTOK;
    __shared__ unsigned s_prefix;
    __shared__ int s_need, s_cnt, s_pos;
    __shared__ int s_eq[1024];
    int tid = threadIdx.x;
    if (tid == 0) { s_prefix = 0u; s_need = CAP; s_pos = 0; }
    __syncthreads();

    for (int bit = 31; bit >= 0; bit--) {
        if (tid == 0) s_cnt = 0;
        __syncthreads();
        unsigned pref = s_prefix;
        unsigned want = (pref >> bit) | 1u;
        int local = 0;
        for (int n = tid; n < NTOK; n += 1024)
            local += ((f2k(col[n]) >> bit) == want);
        for (int o = 16; o > 0; o >>= 1)
            local += __shfl_xor_sync(0xffffffffu, local, o);
        if ((tid & 31) == 0) atomicAdd(&s_cnt, local);
        __syncthreads();
        if (tid == 0) {
            if (s_cnt >= s_need) s_prefix = pref | (1u << bit);
            else                 s_need -= s_cnt;
        }
        __syncthreads();
    }
    unsigned thr = s_prefix;
    int needEq = s_need;
    float mx = g_colmax[e];
    float sm = g_colsum[e];

    // strictly-greater tokens: unordered placement (scatter-add commutes)
    for (int n = tid; n < NTOK; n += 1024) {
        float lv = col[n];
        if (f2k(lv) > thr) {
            int slot = atomicAdd(&s_pos, 1);
            g_idx [e * CAP + slot] = n;
            g_vals[e * CAP + slot] = expf(lv - mx) / sm;
        }
    }
    __syncthreads();
    int G = s_pos;  // == CAP - needEq

    // equal-to-threshold: take lowest indices first via block prefix scan
    int n0 = tid * (NTOK / 1024);
    int cntEq = 0;
    for (int n = n0; n < n0 + NTOK / 1024; n++) cntEq += (f2k(col[n]) == thr);
    s_eq[tid] = cntEq;
    __syncthreads();
    for (int off = 1; off < 1024; off <<= 1) {
        int v = (tid >= off) ? s_eq[tid - off] : 0;
        __syncthreads();
        s_eq[tid] += v;
        __syncthreads();
    }
    int rank = s_eq[tid] - cntEq;  // exclusive prefix
    for (int n = n0; n < n0 + NTOK / 1024; n++) {
        if (f2k(col[n]) == thr) {
            if (rank < needEq) {
                int slot = G + rank;
                g_idx [e * CAP + slot] = n;
                g_vals[e * CAP + slot] = expf(col[n] - mx) / sm;
            }
            rank++;
        }
    }
}

// ---------------- K4: gathered SGEMM1 + bias + exact GELU -> g_h ------------
// h[e][c][f] = gelu( x[idx[e][c]] . W1[e][:, f] + b1[e][f] )
// 128x128x8 block tile, 8x8 per thread, 256 threads.
__global__ __launch_bounds__(256) void k_gemm1(
    const float* __restrict__ x, const float* __restrict__ W1,
    const float* __restrict__ b1)
{
    const int e   = blockIdx.z;
    const int bn0 = blockIdx.x * 128;
    const int bm0 = blockIdx.y * 128;
    const float* Be = W1 + (size_t)e * DDIM * FDIM;

    __shared__ float As[8][128];
    __shared__ float Bs[8][128];

    int tid = threadIdx.x;
    int tx = tid & 15, ty = tid >> 4;

    int aRow = tid >> 1;            // 0..127
    int aCol = (tid & 1) * 4;       // 0 or 4
    int tok  = g_idx[e * CAP + bm0 + aRow];
    const float* arow = x + (size_t)tok * DDIM;

    int bRow = tid >> 5;            // 0..7
    int bCol = (tid & 31) * 4;

    float acc[8][8] = {};
    for (int k0 = 0; k0 < DDIM; k0 += 8) {
        float4 a = *(const float4*)(arow + k0 + aCol);
        As[aCol + 0][aRow] = a.x; As[aCol + 1][aRow] = a.y;
        As[aCol + 2][aRow] = a.z; As[aCol + 3][aRow] = a.w;
        *(float4*)(&Bs[bRow][bCol]) =
            *(const float4*)(Be + (size_t)(k0 + bRow) * FDIM + bn0 + bCol);
        __syncthreads();
#pragma unroll
        for (int kk = 0; kk < 8; kk++) {
            float ra[8], rb[8];
#pragma unroll
            for (int i = 0; i < 8; i++) ra[i] = As[kk][ty * 8 + i];
#pragma unroll
            for (int j = 0; j < 8; j++) rb[j] = Bs[kk][tx * 8 + j];
#pragma unroll
            for (int i = 0; i < 8; i++)
#pragma unroll
                for (int j = 0; j < 8; j++)
                    acc[i][j] += ra[i] * rb[j];
        }
        __syncthreads();
    }
    const float* b1e = b1 + e * FDIM;
#pragma unroll
    for (int i = 0; i < 8; i++) {
        size_t hrow = ((size_t)e * CAP + bm0 + ty * 8 + i) * FDIM;
#pragma unroll
        for (int j = 0; j < 8; j++) {
            int f = bn0 + tx * 8 + j;
            g_h[hrow + f] = gelu_exact(acc[i][j] + b1e[f]);
        }
    }
}

// ---------------- K5: SGEMM2 + bias + val-scale + scatter-add ---------------
// out[idx[e][c]] += vals[e][c] * ( h[e][c] . W2[e][:, d] + b2[e][d] )
__global__ __launch_bounds__(256) void k_gemm2(
    const float* __restrict__ W2, const float* __restrict__ b2,
    float* __restrict__ out)
{
    const int e   = blockIdx.z;
    const int bn0 = blockIdx.x * 128;
    const int bm0 = blockIdx.y * 128;
    const float* Be = W2 + (size_t)e * FDIM * DDIM;

    __shared__ float As[8][128];
    __shared__ float Bs[8][128];

    int tid = threadIdx.x;
    int tx = tid & 15, ty = tid >> 4;

    int aRow = tid >> 1;
    int aCol = (tid & 1) * 4;
    const float* arow = g_h + ((size_t)e * CAP + bm0 + aRow) * FDIM;

    int bRow = tid >> 5;
    int bCol = (tid & 31) * 4;

    float acc[8][8] = {};
    for (int k0 = 0; k0 < FDIM; k0 += 8) {
        float4 a = *(const float4*)(arow + k0 + aCol);
        As[aCol + 0][aRow] = a.x; As[aCol + 1][aRow] = a.y;
        As[aCol + 2][aRow] = a.z; As[aCol + 3][aRow] = a.w;
        *(float4*)(&Bs[bRow][bCol]) =
            *(const float4*)(Be + (size_t)(k0 + bRow) * DDIM + bn0 + bCol);
        __syncthreads();
#pragma unroll
        for (int kk = 0; kk < 8; kk++) {
            float ra[8], rb[8];
#pragma unroll
            for (int i = 0; i < 8; i++) ra[i] = As[kk][ty * 8 + i];
#pragma unroll
            for (int j = 0; j < 8; j++) rb[j] = Bs[kk][tx * 8 + j];
#pragma unroll
            for (int i = 0; i < 8; i++)
#pragma unroll
                for (int j = 0; j < 8; j++)
                    acc[i][j] += ra[i] * rb[j];
        }
        __syncthreads();
    }
    const float* b2e = b2 + e * DDIM;
#pragma unroll
    for (int i = 0; i < 8; i++) {
        int c = bm0 + ty * 8 + i;
        int tok = g_idx[e * CAP + c];
        float v = g_vals[e * CAP + c];
        float* orow = out + (size_t)tok * DDIM;
#pragma unroll
        for (int j = 0; j < 8; j++) {
            int d = bn0 + tx * 8 + j;
            atomicAdd(orow + d, (acc[i][j] + b2e[d]) * v);
        }
    }
}

// ---------------------------------------------------------------------------
extern "C" void kernel_launch(void* const* d_in, const int* in_sizes, int n_in,
                              void* d_out, int out_size)
{
    const float* x  = (const float*)d_in[0];
    const float* Wr = (const float*)d_in[1];
    const float* W1 = (const float*)d_in[2];
    const float* b1 = (const float*)d_in[3];
    const float* W2 = (const float*)d_in[4];
    const float* b2 = (const float*)d_in[5];
    float* out = (float*)d_out;

    cudaMemsetAsync(out, 0, (size_t)NTOK * DDIM * sizeof(float));
    k_logits  <<<NTOK / 8, 256>>>(x, Wr);
    k_colstats<<<NEXP, 512>>>();
    k_select  <<<NEXP, 1024>>>();
    k_gemm1   <<<dim3(FDIM / 128, CAP / 128, NEXP), 256>>>(x, W1, b1);
    k_gemm2   <<<dim3(DDIM / 128, CAP / 128, NEXP), 256>>>(W2, b2, out);
}

// round 4
// speedup vs baseline: 2.2527x; 2.2527x over previous
#include <cuda_runtime.h>
#include <cuda_bf16.h>
#include <math.h>
#include <stdint.h>

#define NTOK 32768   // B*T
#define DDIM 512
#define NEXP 8
#define FDIM 2048
#define CAP  4096

#define BM 128
#define BN 128
#define BK 32
#define STAGES 4
#define STAGE_BYTES 32768          // Ahi 8K | Alo 8K | Bhi 8K | Blo 8K
#define DYN_SMEM (STAGES * STAGE_BYTES + 1024)

// ---------------- device scratch (static; no allocations allowed) -----------
__device__ __align__(128) float g_logitsT[NEXP * NTOK];          // [E][N]
__device__ float g_colmax[NEXP];
__device__ float g_colsum[NEXP];
__device__ __align__(128) int   g_idx [NEXP * CAP];
__device__ __align__(128) float g_vals[NEXP * CAP];
__device__ __align__(128) int   g_tokcnt[NTOK];
__device__ __align__(128) int   g_toklist[NTOK * 8];             // (e*CAP+slot) refs
__device__ __align__(128) __nv_bfloat16 g_xhi[(size_t)NTOK * DDIM];
__device__ __align__(128) __nv_bfloat16 g_xlo[(size_t)NTOK * DDIM];
__device__ __align__(128) __nv_bfloat16 g_w1hi[(size_t)NEXP * FDIM * DDIM]; // W1^T [E][F][D]
__device__ __align__(128) __nv_bfloat16 g_w1lo[(size_t)NEXP * FDIM * DDIM];
__device__ __align__(128) __nv_bfloat16 g_w2hi[(size_t)NEXP * DDIM * FDIM]; // W2^T [E][D][F]
__device__ __align__(128) __nv_bfloat16 g_w2lo[(size_t)NEXP * DDIM * FDIM];
__device__ __align__(128) __nv_bfloat16 g_hhi[(size_t)NEXP * CAP * FDIM];   // h [E][C][F]
__device__ __align__(128) __nv_bfloat16 g_hlo[(size_t)NEXP * CAP * FDIM];
__device__ __align__(128) float g_oute[(size_t)NEXP * CAP * DDIM];          // weighted expert out

// ---------------- small helpers ---------------------------------------------
__device__ __forceinline__ unsigned f2k(float f) {
    unsigned u = __float_as_uint(f);
    return u ^ ((u & 0x80000000u) ? 0xFFFFFFFFu : 0x80000000u);
}
__device__ __forceinline__ float gelu_exact(float v) {
    return 0.5f * v * (1.0f + erff(v * 0.70710678118654752440f));
}
__device__ __forceinline__ uint32_t cvta_smem(const void* p) {
    uint32_t a;
    asm("{ .reg .u64 t; cvta.to.shared.u64 t, %1; cvt.u32.u64 %0, t; }" : "=r"(a) : "l"(p));
    return a;
}
// swizzle for 64-byte rows: XOR 16B-column index (bits 5:4) with row bits (o bits 8:7)
__device__ __forceinline__ uint32_t swz64(uint32_t o) { return o ^ ((o >> 3) & 0x30); }
__device__ __forceinline__ uint32_t packbf(__nv_bfloat16 a, __nv_bfloat16 b) {
    return (uint32_t)__bfloat16_as_ushort(a) | ((uint32_t)__bfloat16_as_ushort(b) << 16);
}

#define CP16(dst, src) asm volatile("cp.async.cg.shared.global [%0], [%1], 16;" :: "r"(dst), "l"(src))
#define CP_COMMIT()    asm volatile("cp.async.commit_group;" ::: "memory")
#define CP_WAIT(n)     asm volatile("cp.async.wait_group %0;" :: "n"(n) : "memory")

__device__ __forceinline__ void ldsm4(uint32_t* r, uint32_t addr) {
    asm volatile("ldmatrix.sync.aligned.m8n8.x4.shared.b16 {%0,%1,%2,%3}, [%4];"
                 : "=r"(r[0]), "=r"(r[1]), "=r"(r[2]), "=r"(r[3]) : "r"(addr));
}
__device__ __forceinline__ void mma16816(float* c, const uint32_t* a, const uint32_t* b) {
    asm volatile(
        "mma.sync.aligned.m16n8k16.row.col.f32.bf16.bf16.f32 "
        "{%0,%1,%2,%3}, {%4,%5,%6,%7}, {%8,%9}, {%0,%1,%2,%3};"
        : "+f"(c[0]), "+f"(c[1]), "+f"(c[2]), "+f"(c[3])
        : "r"(a[0]), "r"(a[1]), "r"(a[2]), "r"(a[3]), "r"(b[0]), "r"(b[1]));
}

// ---------------- K1: logits = x @ Wr, stored transposed [E][N] -------------
__global__ void k_logits(const float* __restrict__ x, const float* __restrict__ Wr)
{
    __shared__ float sW[NEXP * DDIM];
    int tid = threadIdx.x;
    if (tid < 8) g_tokcnt[blockIdx.x * 8 + tid] = 0;   // zero inverse-map counters
    for (int i = tid; i < NEXP * DDIM; i += 256) {
        int e = i >> 9, d = i & 511;
        sW[i] = Wr[d * NEXP + e];
    }
    __syncthreads();
    int warp = tid >> 5, lane = tid & 31;
    int t = blockIdx.x * 8 + warp;
    const float* xr = x + (size_t)t * DDIM;
    float acc[NEXP] = {};
#pragma unroll
    for (int i = 0; i < DDIM / 32; i++) {
        float xv = xr[lane + 32 * i];
#pragma unroll
        for (int e = 0; e < NEXP; e++)
            acc[e] += xv * sW[e * DDIM + lane + 32 * i];
    }
#pragma unroll
    for (int e = 0; e < NEXP; e++) {
#pragma unroll
        for (int o = 16; o > 0; o >>= 1)
            acc[e] += __shfl_xor_sync(0xffffffffu, acc[e], o);
    }
    if (lane == 0) {
#pragma unroll
        for (int e = 0; e < NEXP; e++)
            g_logitsT[e * NTOK + t] = acc[e];
    }
}

// ---------------- K2: per-expert column max + sum(exp) ----------------------
__global__ void k_colstats()
{
    int e = blockIdx.x;
    const float* col = g_logitsT + e * NTOK;
    __shared__ float red[512];
    int tid = threadIdx.x;
    float mx = -INFINITY;
    for (int n = tid; n < NTOK; n += 512) mx = fmaxf(mx, col[n]);
    red[tid] = mx; __syncthreads();
    for (int s = 256; s > 0; s >>= 1) {
        if (tid < s) red[tid] = fmaxf(red[tid], red[tid + s]);
        __syncthreads();
    }
    mx = red[0]; __syncthreads();
    float sm = 0.f;
    for (int n = tid; n < NTOK; n += 512) sm += expf(col[n] - mx);
    red[tid] = sm; __syncthreads();
    for (int s = 256; s > 0; s >>= 1) {
        if (tid < s) red[tid] += red[tid + s];
        __syncthreads();
    }
    if (tid == 0) { g_colmax[e] = mx; g_colsum[e] = red[0]; }
}

// ---------------- K3: per-expert exact top-CAP via radix select -------------
__global__ void k_select()
{
    int e = blockIdx.x;
    const float* col = g_logitsT + e * NTOK;
    __shared__ unsigned s_prefix;
    __shared__ int s_need, s_cnt, s_pos;
    __shared__ int s_eq[1024];
    int tid = threadIdx.x;
    if (tid == 0) { s_prefix = 0u; s_need = CAP; s_pos = 0; }
    __syncthreads();

    for (int bit = 31; bit >= 0; bit--) {
        if (tid == 0) s_cnt = 0;
        __syncthreads();
        unsigned pref = s_prefix;
        unsigned want = (pref >> bit) | 1u;
        int local = 0;
        for (int n = tid; n < NTOK; n += 1024)
            local += ((f2k(col[n]) >> bit) == want);
        for (int o = 16; o > 0; o >>= 1)
            local += __shfl_xor_sync(0xffffffffu, local, o);
        if ((tid & 31) == 0) atomicAdd(&s_cnt, local);
        __syncthreads();
        if (tid == 0) {
            if (s_cnt >= s_need) s_prefix = pref | (1u << bit);
            else                 s_need -= s_cnt;
        }
        __syncthreads();
    }
    unsigned thr = s_prefix;
    int needEq = s_need;
    float mx = g_colmax[e];
    float sm = g_colsum[e];

    for (int n = tid; n < NTOK; n += 1024) {
        float lv = col[n];
        if (f2k(lv) > thr) {
            int slot = atomicAdd(&s_pos, 1);
            g_idx [e * CAP + slot] = n;
            g_vals[e * CAP + slot] = expf(lv - mx) / sm;
            int p = atomicAdd(&g_tokcnt[n], 1);
            g_toklist[n * 8 + p] = e * CAP + slot;
        }
    }
    __syncthreads();
    int G = s_pos;

    int n0 = tid * (NTOK / 1024);
    int cntEq = 0;
    for (int n = n0; n < n0 + NTOK / 1024; n++) cntEq += (f2k(col[n]) == thr);
    s_eq[tid] = cntEq;
    __syncthreads();
    for (int off = 1; off < 1024; off <<= 1) {
        int v = (tid >= off) ? s_eq[tid - off] : 0;
        __syncthreads();
        s_eq[tid] += v;
        __syncthreads();
    }
    int rank = s_eq[tid] - cntEq;
    for (int n = n0; n < n0 + NTOK / 1024; n++) {
        if (f2k(col[n]) == thr) {
            if (rank < needEq) {
                int slot = G + rank;
                g_idx [e * CAP + slot] = n;
                g_vals[e * CAP + slot] = expf(col[n] - mx) / sm;
                int p = atomicAdd(&g_tokcnt[n], 1);
                g_toklist[n * 8 + p] = e * CAP + slot;
            }
            rank++;
        }
    }
}

// ---------------- converts ---------------------------------------------------
__global__ void k_cvt_x(const float4* __restrict__ x)
{
    int i = blockIdx.x * 256 + threadIdx.x;     // over NTOK*DDIM/4
    float4 v = x[i];
    __nv_bfloat16 h0 = __float2bfloat16(v.x), h1 = __float2bfloat16(v.y);
    __nv_bfloat16 h2 = __float2bfloat16(v.z), h3 = __float2bfloat16(v.w);
    __nv_bfloat16 l0 = __float2bfloat16(v.x - __bfloat162float(h0));
    __nv_bfloat16 l1 = __float2bfloat16(v.y - __bfloat162float(h1));
    __nv_bfloat16 l2 = __float2bfloat16(v.z - __bfloat162float(h2));
    __nv_bfloat16 l3 = __float2bfloat16(v.w - __bfloat162float(h3));
    uint2 ph, pl;
    ph.x = packbf(h0, h1); ph.y = packbf(h2, h3);
    pl.x = packbf(l0, l1); pl.y = packbf(l2, l3);
    ((uint2*)g_xhi)[i] = ph;
    ((uint2*)g_xlo)[i] = pl;
}

// transpose W1 [E][D][F] -> W1^T [E][F][D], hi/lo bf16
__global__ void k_cvt_w1(const float* __restrict__ W1)
{
    __shared__ float t[32][33];
    const int R = DDIM, C = FDIM;
    int e = blockIdx.z;
    const float* S = W1 + (size_t)e * R * C;
    int c0 = blockIdx.x * 32, r0 = blockIdx.y * 32;
    int tx = threadIdx.x, ty = threadIdx.y;
#pragma unroll
    for (int i = 0; i < 4; i++)
        t[ty + 8 * i][tx] = S[(size_t)(r0 + ty + 8 * i) * C + c0 + tx];
    __syncthreads();
#pragma unroll
    for (int i = 0; i < 4; i++) {
        float v = t[tx][ty + 8 * i];
        __nv_bfloat16 h = __float2bfloat16(v);
        __nv_bfloat16 l = __float2bfloat16(v - __bfloat162float(h));
        size_t o = (size_t)e * C * R + (size_t)(c0 + ty + 8 * i) * R + r0 + tx;
        g_w1hi[o] = h; g_w1lo[o] = l;
    }
}

// transpose W2 [E][F][D] -> W2^T [E][D][F], hi/lo bf16
__global__ void k_cvt_w2(const float* __restrict__ W2)
{
    __shared__ float t[32][33];
    const int R = FDIM, C = DDIM;
    int e = blockIdx.z;
    const float* S = W2 + (size_t)e * R * C;
    int c0 = blockIdx.x * 32, r0 = blockIdx.y * 32;
    int tx = threadIdx.x, ty = threadIdx.y;
#pragma unroll
    for (int i = 0; i < 4; i++)
        t[ty + 8 * i][tx] = S[(size_t)(r0 + ty + 8 * i) * C + c0 + tx];
    __syncthreads();
#pragma unroll
    for (int i = 0; i < 4; i++) {
        float v = t[tx][ty + 8 * i];
        __nv_bfloat16 h = __float2bfloat16(v);
        __nv_bfloat16 l = __float2bfloat16(v - __bfloat162float(h));
        size_t o = (size_t)e * C * R + (size_t)(c0 + ty + 8 * i) * R + r0 + tx;
        g_w2hi[o] = h; g_w2lo[o] = l;
    }
}

// ================== mma.sync GEMM mainloop helpers ==========================
struct FragState {
    uint32_t aoff[2][2];   // [mfrag][kk]  region-relative swizzled offsets
    uint32_t boff[4][2];   // [nf2][kk]
};
__device__ __forceinline__ void frag_offsets(FragState& fs, int lane, int mwarp, int nwarp)
{
    int r16 = lane & 15, hi16 = (lane >> 4) * 16;
#pragma unroll
    for (int mf = 0; mf < 2; mf++)
#pragma unroll
        for (int kk = 0; kk < 2; kk++)
            fs.aoff[mf][kk] = swz64((uint32_t)((mwarp * 32 + mf * 16 + r16) * 64 + kk * 32 + hi16));
#pragma unroll
    for (int nf2 = 0; nf2 < 4; nf2++)
#pragma unroll
        for (int kk = 0; kk < 2; kk++)
            fs.boff[nf2][kk] = swz64((uint32_t)((nwarp * 64 + nf2 * 16 + r16) * 64 + kk * 32 + hi16));
}

__device__ __forceinline__ void compute_stage(float c[2][8][4], const FragState& fs,
                                              uint32_t abase, uint32_t bbase)
{
#pragma unroll
    for (int kk = 0; kk < 2; kk++) {
        uint32_t ah[2][4], al[2][4], bh[8][2], bl[8][2];
#pragma unroll
        for (int mf = 0; mf < 2; mf++) {
            ldsm4(ah[mf], abase + fs.aoff[mf][kk]);
            ldsm4(al[mf], abase + 8192 + fs.aoff[mf][kk]);
        }
#pragma unroll
        for (int nf2 = 0; nf2 < 4; nf2++) {
            uint32_t r[4];
            ldsm4(r, bbase + fs.boff[nf2][kk]);
            bh[2 * nf2][0] = r[0]; bh[2 * nf2][1] = r[2];
            bh[2 * nf2 + 1][0] = r[1]; bh[2 * nf2 + 1][1] = r[3];
            ldsm4(r, bbase + 8192 + fs.boff[nf2][kk]);
            bl[2 * nf2][0] = r[0]; bl[2 * nf2][1] = r[2];
            bl[2 * nf2 + 1][0] = r[1]; bl[2 * nf2 + 1][1] = r[3];
        }
#pragma unroll
        for (int mf = 0; mf < 2; mf++)
#pragma unroll
            for (int nf = 0; nf < 8; nf++) {
                mma16816(c[mf][nf], ah[mf], bh[nf]);
                mma16816(c[mf][nf], ah[mf], bl[nf]);
                mma16816(c[mf][nf], al[mf], bh[nf]);
            }
    }
}

// ---------------- GEMM1: h = gelu(gather(x) @ W1 + b1) ----------------------
__device__ __forceinline__ void g1_load(int tid, const int* s_tok, int e, int bn0,
                                        uint32_t dynb, int kt, int st)
{
    int k0 = kt * BK;
    uint32_t base = dynb + st * STAGE_BYTES;
#pragma unroll
    for (int t = tid; t < 512; t += 256) {
        int row = t >> 2, cc = t & 3;
        uint32_t o = swz64((uint32_t)(row * 64 + cc * 16));
        size_t ga = (size_t)s_tok[row] * DDIM + k0 + cc * 8;
        CP16(base + o, g_xhi + ga);
        CP16(base + 8192 + o, g_xlo + ga);
        size_t gb = (size_t)(e * FDIM + bn0 + row) * DDIM + k0 + cc * 8;
        CP16(base + 16384 + o, g_w1hi + gb);
        CP16(base + 24576 + o, g_w1lo + gb);
    }
}

__global__ __launch_bounds__(256, 1) void k_gemm1_mma(const float* __restrict__ b1)
{
    extern __shared__ __align__(16) unsigned char dynraw[];
    __shared__ int s_tok[BM];
    __shared__ float s_bias[BN];

    const int tid = threadIdx.x, wid = tid >> 5, lane = tid & 31;
    const int mwarp = wid & 3, nwarp = wid >> 2;
    const int e = blockIdx.z, bn0 = blockIdx.x * BN, bm0 = blockIdx.y * BM;

    uint32_t rawb = cvta_smem(dynraw);
    uint32_t pad = (1024u - (rawb & 1023u)) & 1023u;
    uint32_t dynb = rawb + pad;
    unsigned char* dynp = dynraw + pad;

    if (tid < BM) s_tok[tid] = g_idx[e * CAP + bm0 + tid];
    if (tid < BN) s_bias[tid] = b1[e * FDIM + bn0 + tid];
    __syncthreads();

    FragState fs;
    frag_offsets(fs, lane, mwarp, nwarp);
    float c[2][8][4] = {};

    const int KT = DDIM / BK;  // 16
    g1_load(tid, s_tok, e, bn0, dynb, 0, 0); CP_COMMIT();
    g1_load(tid, s_tok, e, bn0, dynb, 1, 1); CP_COMMIT();
    g1_load(tid, s_tok, e, bn0, dynb, 2, 2); CP_COMMIT();

    for (int kt = 0; kt < KT; kt++) {
        CP_WAIT(2);
        __syncthreads();
        if (kt + STAGES - 1 < KT)
            g1_load(tid, s_tok, e, bn0, dynb, kt + STAGES - 1, (kt + STAGES - 1) & 3);
        CP_COMMIT();
        uint32_t abase = dynb + (kt & 3) * STAGE_BYTES;
        compute_stage(c, fs, abase, abase + 16384);
    }
    __syncthreads();   // all warps done with stages before epilogue reuses smem

    // epilogue: gelu -> bf16 hi/lo -> smem stage -> coalesced 16B stores
#pragma unroll
    for (int mf = 0; mf < 2; mf++)
#pragma unroll
        for (int nf = 0; nf < 8; nf++)
#pragma unroll
            for (int half = 0; half < 2; half++) {
                int row = mwarp * 32 + mf * 16 + (lane >> 2) + half * 8;
                int col = nwarp * 64 + nf * 8 + (lane & 3) * 2;
                float v0 = c[mf][nf][half * 2 + 0] + s_bias[col];
                float v1 = c[mf][nf][half * 2 + 1] + s_bias[col + 1];
                float gg0 = gelu_exact(v0), gg1 = gelu_exact(v1);
                __nv_bfloat16 h0 = __float2bfloat16(gg0), h1 = __float2bfloat16(gg1);
                __nv_bfloat16 l0 = __float2bfloat16(gg0 - __bfloat162float(h0));
                __nv_bfloat16 l1 = __float2bfloat16(gg1 - __bfloat162float(h1));
                uint32_t off = (uint32_t)row * 256 + (((uint32_t)col * 2) ^ (((uint32_t)row & 15) << 4));
                *(uint32_t*)(dynp + off)         = packbf(h0, h1);
                *(uint32_t*)(dynp + 32768 + off) = packbf(l0, l1);
            }
    __syncthreads();
#pragma unroll
    for (int it = 0; it < 8; it++) {
        int g = tid + it * 256;                  // 2048 16B chunks per buffer
        int r2 = g >> 4, seg = g & 15;
        uint32_t off = (uint32_t)r2 * 256 + (((uint32_t)seg * 16) ^ (((uint32_t)r2 & 15) << 4));
        uint4 vh = *(const uint4*)(dynp + off);
        uint4 vl = *(const uint4*)(dynp + 32768 + off);
        size_t hb = ((size_t)(e * CAP + bm0 + r2)) * FDIM + bn0;
        *(uint4*)((char*)g_hhi + hb * 2 + seg * 16) = vh;
        *(uint4*)((char*)g_hlo + hb * 2 + seg * 16) = vl;
    }
}

// ---------------- GEMM2: oute = (h @ W2 + b2) * vals ------------------------
__device__ __forceinline__ void g2_load(int tid, int e, int bn0, int bm0,
                                        uint32_t dynb, int kt, int st)
{
    int k0 = kt * BK;
    uint32_t base = dynb + st * STAGE_BYTES;
#pragma unroll
    for (int t = tid; t < 512; t += 256) {
        int row = t >> 2, cc = t & 3;
        uint32_t o = swz64((uint32_t)(row * 64 + cc * 16));
        size_t ga = (size_t)(e * CAP + bm0 + row) * FDIM + k0 + cc * 8;
        CP16(base + o, g_hhi + ga);
        CP16(base + 8192 + o, g_hlo + ga);
        size_t gb = (size_t)(e * DDIM + bn0 + row) * FDIM + k0 + cc * 8;
        CP16(base + 16384 + o, g_w2hi + gb);
        CP16(base + 24576 + o, g_w2lo + gb);
    }
}

__global__ __launch_bounds__(256, 1) void k_gemm2_mma(const float* __restrict__ b2)
{
    extern __shared__ __align__(16) unsigned char dynraw[];
    __shared__ float s_val[BM];
    __shared__ float s_bias[BN];

    const int tid = threadIdx.x, wid = tid >> 5, lane = tid & 31;
    const int mwarp = wid & 3, nwarp = wid >> 2;
    const int e = blockIdx.z, bn0 = blockIdx.x * BN, bm0 = blockIdx.y * BM;

    uint32_t rawb = cvta_smem(dynraw);
    uint32_t pad = (1024u - (rawb & 1023u)) & 1023u;
    uint32_t dynb = rawb + pad;
    unsigned char* dynp = dynraw + pad;

    if (tid < BM) s_val[tid] = g_vals[e * CAP + bm0 + tid];
    if (tid < BN) s_bias[tid] = b2[e * DDIM + bn0 + tid];
    __syncthreads();

    FragState fs;
    frag_offsets(fs, lane, mwarp, nwarp);
    float c[2][8][4] = {};

    const int KT = FDIM / BK;  // 64
    g2_load(tid, e, bn0, bm0, dynb, 0, 0); CP_COMMIT();
    g2_load(tid, e, bn0, bm0, dynb, 1, 1); CP_COMMIT();
    g2_load(tid, e, bn0, bm0, dynb, 2, 2); CP_COMMIT();

    for (int kt = 0; kt < KT; kt++) {
        CP_WAIT(2);
        __syncthreads();
        if (kt + STAGES - 1 < KT)
            g2_load(tid, e, bn0, bm0, dynb, kt + STAGES - 1, (kt + STAGES - 1) & 3);
        CP_COMMIT();
        uint32_t abase = dynb + (kt & 3) * STAGE_BYTES;
        compute_stage(c, fs, abase, abase + 16384);
    }
    __syncthreads();

    // epilogue: (acc + b2) * val -> f32 smem stage (512B/row) -> 16B stores
#pragma unroll
    for (int mf = 0; mf < 2; mf++)
#pragma unroll
        for (int nf = 0; nf < 8; nf++)
#pragma unroll
            for (int half = 0; half < 2; half++) {
                int row = mwarp * 32 + mf * 16 + (lane >> 2) + half * 8;
                int col = nwarp * 64 + nf * 8 + (lane & 3) * 2;
                float vr = s_val[row];
                float2 o2;
                o2.x = (c[mf][nf][half * 2 + 0] + s_bias[col]) * vr;
                o2.y = (c[mf][nf][half * 2 + 1] + s_bias[col + 1]) * vr;
                uint32_t off = (uint32_t)row * 512 + (((uint32_t)col * 4) ^ (((uint32_t)row & 31) << 4));
                *(float2*)(dynp + off) = o2;
            }
    __syncthreads();
#pragma unroll
    for (int it = 0; it < 16; it++) {
        int g = tid + it * 256;                  // 4096 16B chunks
        int r2 = g >> 5, seg = g & 31;
        uint32_t off = (uint32_t)r2 * 512 + (((uint32_t)seg * 16) ^ (((uint32_t)r2 & 31) << 4));
        uint4 v = *(const uint4*)(dynp + off);
        size_t ob = ((size_t)(e * CAP + bm0 + r2)) * DDIM + bn0;
        *(uint4*)((char*)g_oute + ob * 4 + seg * 16) = v;
    }
}

// ---------------- K6: gather-reduce scatter to output -----------------------
__global__ void k_scatter(float* __restrict__ out)
{
    int t = blockIdx.x * 2 + (threadIdx.x >> 7);
    int l = threadIdx.x & 127;
    int cnt = g_tokcnt[t];
    float4 acc = make_float4(0.f, 0.f, 0.f, 0.f);
    for (int i = 0; i < cnt; i++) {
        int ref = g_toklist[t * 8 + i];
        float4 v = ((const float4*)(g_oute + (size_t)ref * DDIM))[l];
        acc.x += v.x; acc.y += v.y; acc.z += v.z; acc.w += v.w;
    }
    ((float4*)out)[(size_t)t * (DDIM / 4) + l] = acc;
}

// ---------------------------------------------------------------------------
extern "C" void kernel_launch(void* const* d_in, const int* in_sizes, int n_in,
                              void* d_out, int out_size)
{
    const float* x  = (const float*)d_in[0];
    const float* Wr = (const float*)d_in[1];
    const float* W1 = (const float*)d_in[2];
    const float* b1 = (const float*)d_in[3];
    const float* W2 = (const float*)d_in[4];
    const float* b2 = (const float*)d_in[5];
    float* out = (float*)d_out;

    cudaFuncSetAttribute(k_gemm1_mma, cudaFuncAttributeMaxDynamicSharedMemorySize, DYN_SMEM);
    cudaFuncSetAttribute(k_gemm2_mma, cudaFuncAttributeMaxDynamicSharedMemorySize, DYN_SMEM);

    k_cvt_x   <<<NTOK * DDIM / 1024, 256>>>((const float4*)x);
    k_cvt_w1  <<<dim3(FDIM / 32, DDIM / 32, NEXP), dim3(32, 8)>>>(W1);
    k_cvt_w2  <<<dim3(DDIM / 32, FDIM / 32, NEXP), dim3(32, 8)>>>(W2);
    k_logits  <<<NTOK / 8, 256>>>(x, Wr);
    k_colstats<<<NEXP, 512>>>();
    k_select  <<<NEXP, 1024>>>();
    k_gemm1_mma<<<dim3(FDIM / BN, CAP / BM, NEXP), 256, DYN_SMEM>>>(b1);
    k_gemm2_mma<<<dim3(DDIM / BN, CAP / BM, NEXP), 256, DYN_SMEM>>>(b2);
    k_scatter <<<NTOK / 2, 256>>>(out);
}

// round 5
// speedup vs baseline: 5.3700x; 2.3838x over previous
#include <cuda_runtime.h>
#include <cuda_fp16.h>
#include <math.h>
#include <stdint.h>

#define NTOK 32768   // B*T
#define DDIM 512
#define NEXP 8
#define FDIM 2048
#define CAP  4096

#define BM 128
#define BN 128
#define BK 32
#define STAGES 4
#define STAGE_BYTES 16384          // A 8K | B 8K   (fp16 single)
#define DYN_SMEM (STAGES * STAGE_BYTES + 1024)

// ---------------- device scratch (static; no allocations allowed) -----------
__device__ __align__(128) float g_logitsT[NEXP * NTOK];          // [E][N]
__device__ float g_colmax[NEXP];
__device__ float g_colsum[NEXP];
__device__ __align__(128) int   g_idx [NEXP * CAP];
__device__ __align__(128) float g_vals[NEXP * CAP];
__device__ __align__(128) int   g_tokcnt[NTOK];
__device__ __align__(128) int   g_toklist[NTOK * 8];             // (e*CAP+slot) refs
__device__ __align__(128) __half g_xh [(size_t)NTOK * DDIM];
__device__ __align__(128) __half g_w1h[(size_t)NEXP * FDIM * DDIM]; // W1^T [E][F][D]
__device__ __align__(128) __half g_w2h[(size_t)NEXP * DDIM * FDIM]; // W2^T [E][D][F]
__device__ __align__(128) __half g_hh [(size_t)NEXP * CAP * FDIM];  // h [E][C][F]
__device__ __align__(128) float g_oute[(size_t)NEXP * CAP * DDIM];  // weighted expert out

// ---------------- small helpers ---------------------------------------------
__device__ __forceinline__ unsigned f2k(float f) {
    unsigned u = __float_as_uint(f);
    return u ^ ((u & 0x80000000u) ? 0xFFFFFFFFu : 0x80000000u);
}
__device__ __forceinline__ float gelu_exact(float v) {
    return 0.5f * v * (1.0f + erff(v * 0.70710678118654752440f));
}
__device__ __forceinline__ uint32_t cvta_smem(const void* p) {
    uint32_t a;
    asm("{ .reg .u64 t; cvta.to.shared.u64 t, %1; cvt.u32.u64 %0, t; }" : "=r"(a) : "l"(p));
    return a;
}
// swizzle for 64-byte rows: XOR 16B-col index (bits 5:4) with row bits (o bits 8:7)
__device__ __forceinline__ uint32_t swz64(uint32_t o) { return o ^ ((o >> 3) & 0x30); }
__device__ __forceinline__ uint32_t packh(__half a, __half b) {
    return (uint32_t)__half_as_ushort(a) | ((uint32_t)__half_as_ushort(b) << 16);
}

#define CP16(dst, src) asm volatile("cp.async.cg.shared.global [%0], [%1], 16;" :: "r"(dst), "l"(src))
#define CP_COMMIT()    asm volatile("cp.async.commit_group;" ::: "memory")
#define CP_WAIT(n)     asm volatile("cp.async.wait_group %0;" :: "n"(n) : "memory")

__device__ __forceinline__ void ldsm4(uint32_t* r, uint32_t addr) {
    asm volatile("ldmatrix.sync.aligned.m8n8.x4.shared.b16 {%0,%1,%2,%3}, [%4];"
                 : "=r"(r[0]), "=r"(r[1]), "=r"(r[2]), "=r"(r[3]) : "r"(addr));
}
__device__ __forceinline__ void mma16816(float* c, const uint32_t* a, const uint32_t* b) {
    asm volatile(
        "mma.sync.aligned.m16n8k16.row.col.f32.f16.f16.f32 "
        "{%0,%1,%2,%3}, {%4,%5,%6,%7}, {%8,%9}, {%0,%1,%2,%3};"
        : "+f"(c[0]), "+f"(c[1]), "+f"(c[2]), "+f"(c[3])
        : "r"(a[0]), "r"(a[1]), "r"(a[2]), "r"(a[3]), "r"(b[0]), "r"(b[1]));
}

// ---------------- K1: logits = x @ Wr, stored transposed [E][N] -------------
__global__ void k_logits(const float* __restrict__ x, const float* __restrict__ Wr)
{
    __shared__ float sW[NEXP * DDIM];   // [e][d]
    int tid = threadIdx.x;
    if (tid < 8) g_tokcnt[blockIdx.x * 8 + tid] = 0;   // zero inverse-map counters
    for (int i = tid; i < NEXP * DDIM; i += 256) {
        int e = i >> 9, d = i & 511;
        sW[i] = Wr[d * NEXP + e];
    }
    __syncthreads();
    int warp = tid >> 5, lane = tid & 31;
    int t = blockIdx.x * 8 + warp;
    const float4* xr4 = (const float4*)(x + (size_t)t * DDIM);
    float acc[NEXP] = {};
#pragma unroll
    for (int i = 0; i < 4; i++) {
        float4 xv = xr4[lane + 32 * i];
        int d = (lane + 32 * i) * 4;
#pragma unroll
        for (int e = 0; e < NEXP; e++) {
            float4 w = *(const float4*)&sW[e * DDIM + d];   // ld.shared.v4, conflict-free
            acc[e] += xv.x * w.x + xv.y * w.y + xv.z * w.z + xv.w * w.w;
        }
    }
#pragma unroll
    for (int e = 0; e < NEXP; e++) {
#pragma unroll
        for (int o = 16; o > 0; o >>= 1)
            acc[e] += __shfl_xor_sync(0xffffffffu, acc[e], o);
    }
    if (lane == 0) {
#pragma unroll
        for (int e = 0; e < NEXP; e++)
            g_logitsT[e * NTOK + t] = acc[e];
    }
}

// ---------------- K2: per-expert column max + sum(exp) ----------------------
__global__ void k_colstats()
{
    int e = blockIdx.x;
    const float* col = g_logitsT + e * NTOK;
    __shared__ float red[512];
    int tid = threadIdx.x;
    float mx = -INFINITY;
    for (int n = tid; n < NTOK; n += 512) mx = fmaxf(mx, col[n]);
    red[tid] = mx; __syncthreads();
    for (int s = 256; s > 0; s >>= 1) {
        if (tid < s) red[tid] = fmaxf(red[tid], red[tid + s]);
        __syncthreads();
    }
    mx = red[0]; __syncthreads();
    float sm = 0.f;
    for (int n = tid; n < NTOK; n += 512) sm += expf(col[n] - mx);
    red[tid] = sm; __syncthreads();
    for (int s = 256; s > 0; s >>= 1) {
        if (tid < s) red[tid] += red[tid + s];
        __syncthreads();
    }
    if (tid == 0) { g_colmax[e] = mx; g_colsum[e] = red[0]; }
}

// ---------------- K3: per-expert exact top-CAP via 8-bit histogram radix ----
__global__ void k_select()
{
    int e = blockIdx.x;
    const float* col = g_logitsT + e * NTOK;
    __shared__ int s_hist[256];
    __shared__ unsigned s_prefix;
    __shared__ int s_need, s_pos;
    __shared__ int s_eq[1024];
    int tid = threadIdx.x;
    if (tid == 0) { s_prefix = 0u; s_need = CAP; s_pos = 0; }

#pragma unroll
    for (int shift = 24; shift >= 0; shift -= 8) {
        if (tid < 256) s_hist[tid] = 0;
        __syncthreads();
        unsigned pref = s_prefix;
        unsigned maskH = (shift == 24) ? 0u : (0xFFFFFFFFu << (shift + 8));
        for (int n = tid; n < NTOK; n += 1024) {
            unsigned k = f2k(col[n]);
            if ((k & maskH) == pref)
                atomicAdd(&s_hist[(k >> shift) & 255], 1);
        }
        __syncthreads();
        if (tid == 0) {
            int need = s_need, cum = 0, b = 255;
            for (; b > 0; b--) { cum += s_hist[b]; if (cum >= need) break; }
            if (cum < need) cum += s_hist[0];           // b == 0 fallthrough
            s_need = need - (cum - s_hist[b]);
            s_prefix = pref | ((unsigned)b << shift);
        }
        __syncthreads();
    }
    unsigned thr = s_prefix;
    int needEq = s_need;
    float mx = g_colmax[e];
    float sm = g_colsum[e];

    // strictly-greater tokens: unordered placement (scatter-add commutes)
    for (int n = tid; n < NTOK; n += 1024) {
        float lv = col[n];
        if (f2k(lv) > thr) {
            int slot = atomicAdd(&s_pos, 1);
            g_idx [e * CAP + slot] = n;
            g_vals[e * CAP + slot] = expf(lv - mx) / sm;
            int p = atomicAdd(&g_tokcnt[n], 1);
            g_toklist[n * 8 + p] = e * CAP + slot;
        }
    }
    __syncthreads();
    int G = s_pos;

    // equal-to-threshold: lowest indices first via block prefix scan
    int n0 = tid * (NTOK / 1024);
    int cntEq = 0;
    for (int n = n0; n < n0 + NTOK / 1024; n++) cntEq += (f2k(col[n]) == thr);
    s_eq[tid] = cntEq;
    __syncthreads();
    for (int off = 1; off < 1024; off <<= 1) {
        int v = (tid >= off) ? s_eq[tid - off] : 0;
        __syncthreads();
        s_eq[tid] += v;
        __syncthreads();
    }
    int rank = s_eq[tid] - cntEq;
    for (int n = n0; n < n0 + NTOK / 1024; n++) {
        if (f2k(col[n]) == thr) {
            if (rank < needEq) {
                int slot = G + rank;
                g_idx [e * CAP + slot] = n;
                g_vals[e * CAP + slot] = expf(col[n] - mx) / sm;
                int p = atomicAdd(&g_tokcnt[n], 1);
                g_toklist[n * 8 + p] = e * CAP + slot;
            }
            rank++;
        }
    }
}

// ---------------- converts ---------------------------------------------------
__global__ void k_cvt_x(const float4* __restrict__ x)
{
    int i = blockIdx.x * 256 + threadIdx.x;     // over NTOK*DDIM/4
    float4 v = x[i];
    uint2 p;
    p.x = packh(__float2half(v.x), __float2half(v.y));
    p.y = packh(__float2half(v.z), __float2half(v.w));
    ((uint2*)g_xh)[i] = p;
}

// transpose W1 [E][D][F] -> W1^T [E][F][D], fp16
__global__ void k_cvt_w1(const float* __restrict__ W1)
{
    __shared__ float t[32][33];
    const int R = DDIM, C = FDIM;
    int e = blockIdx.z;
    const float* S = W1 + (size_t)e * R * C;
    int c0 = blockIdx.x * 32, r0 = blockIdx.y * 32;
    int tx = threadIdx.x, ty = threadIdx.y;
#pragma unroll
    for (int i = 0; i < 4; i++)
        t[ty + 8 * i][tx] = S[(size_t)(r0 + ty + 8 * i) * C + c0 + tx];
    __syncthreads();
#pragma unroll
    for (int i = 0; i < 4; i++) {
        float v = t[tx][ty + 8 * i];
        size_t o = (size_t)e * C * R + (size_t)(c0 + ty + 8 * i) * R + r0 + tx;
        g_w1h[o] = __float2half(v);
    }
}

// transpose W2 [E][F][D] -> W2^T [E][D][F], fp16
__global__ void k_cvt_w2(const float* __restrict__ W2)
{
    __shared__ float t[32][33];
    const int R = FDIM, C = DDIM;
    int e = blockIdx.z;
    const float* S = W2 + (size_t)e * R * C;
    int c0 = blockIdx.x * 32, r0 = blockIdx.y * 32;
    int tx = threadIdx.x, ty = threadIdx.y;
#pragma unroll
    for (int i = 0; i < 4; i++)
        t[ty + 8 * i][tx] = S[(size_t)(r0 + ty + 8 * i) * C + c0 + tx];
    __syncthreads();
#pragma unroll
    for (int i = 0; i < 4; i++) {
        float v = t[tx][ty + 8 * i];
        size_t o = (size_t)e * C * R + (size_t)(c0 + ty + 8 * i) * R + r0 + tx;
        g_w2h[o] = __float2half(v);
    }
}

// ================== mma.sync GEMM mainloop helpers ==========================
struct FragState {
    uint32_t aoff[2][2];   // [mfrag][kk]  region-relative swizzled offsets
    uint32_t boff[4][2];   // [nf2][kk]
};
__device__ __forceinline__ void frag_offsets(FragState& fs, int lane, int mwarp, int nwarp)
{
    int r16 = lane & 15, hi16 = (lane >> 4) * 16;
#pragma unroll
    for (int mf = 0; mf < 2; mf++)
#pragma unroll
        for (int kk = 0; kk < 2; kk++)
            fs.aoff[mf][kk] = swz64((uint32_t)((mwarp * 32 + mf * 16 + r16) * 64 + kk * 32 + hi16));
#pragma unroll
    for (int nf2 = 0; nf2 < 4; nf2++)
#pragma unroll
        for (int kk = 0; kk < 2; kk++)
            fs.boff[nf2][kk] = swz64((uint32_t)((nwarp * 64 + nf2 * 16 + r16) * 64 + kk * 32 + hi16));
}

__device__ __forceinline__ void compute_stage(float c[2][8][4], const FragState& fs,
                                              uint32_t abase)
{
    const uint32_t bbase = abase + 8192;
#pragma unroll
    for (int kk = 0; kk < 2; kk++) {
        uint32_t a[2][4], b[8][2];
#pragma unroll
        for (int mf = 0; mf < 2; mf++)
            ldsm4(a[mf], abase + fs.aoff[mf][kk]);
#pragma unroll
        for (int nf2 = 0; nf2 < 4; nf2++) {
            uint32_t r[4];
            ldsm4(r, bbase + fs.boff[nf2][kk]);
            b[2 * nf2][0] = r[0]; b[2 * nf2][1] = r[2];
            b[2 * nf2 + 1][0] = r[1]; b[2 * nf2 + 1][1] = r[3];
        }
#pragma unroll
        for (int mf = 0; mf < 2; mf++)
#pragma unroll
            for (int nf = 0; nf < 8; nf++)
                mma16816(c[mf][nf], a[mf], b[nf]);
    }
}

// ---------------- GEMM1: h = gelu(gather(x) @ W1 + b1) ----------------------
__device__ __forceinline__ void g1_load(int tid, const int* s_tok, int e, int bn0,
                                        uint32_t dynb, int kt, int st)
{
    int k0 = kt * BK;
    uint32_t base = dynb + st * STAGE_BYTES;
#pragma unroll
    for (int t = tid; t < 512; t += 256) {
        int row = t >> 2, cc = t & 3;
        uint32_t o = swz64((uint32_t)(row * 64 + cc * 16));
        size_t ga = (size_t)s_tok[row] * DDIM + k0 + cc * 8;
        CP16(base + o, g_xh + ga);
        size_t gb = (size_t)(e * FDIM + bn0 + row) * DDIM + k0 + cc * 8;
        CP16(base + 8192 + o, g_w1h + gb);
    }
}

__global__ __launch_bounds__(256, 2) void k_gemm1_mma(const float* __restrict__ b1)
{
    extern __shared__ __align__(16) unsigned char dynraw[];
    __shared__ int s_tok[BM];
    __shared__ float s_bias[BN];

    const int tid = threadIdx.x, wid = tid >> 5, lane = tid & 31;
    const int mwarp = wid & 3, nwarp = wid >> 2;
    const int e = blockIdx.z, bn0 = blockIdx.x * BN, bm0 = blockIdx.y * BM;

    uint32_t rawb = cvta_smem(dynraw);
    uint32_t pad = (1024u - (rawb & 1023u)) & 1023u;
    uint32_t dynb = rawb + pad;
    unsigned char* dynp = dynraw + pad;

    if (tid < BM) s_tok[tid] = g_idx[e * CAP + bm0 + tid];
    if (tid < BN) s_bias[tid] = b1[e * FDIM + bn0 + tid];
    __syncthreads();

    FragState fs;
    frag_offsets(fs, lane, mwarp, nwarp);
    float c[2][8][4] = {};

    const int KT = DDIM / BK;  // 16
    g1_load(tid, s_tok, e, bn0, dynb, 0, 0); CP_COMMIT();
    g1_load(tid, s_tok, e, bn0, dynb, 1, 1); CP_COMMIT();
    g1_load(tid, s_tok, e, bn0, dynb, 2, 2); CP_COMMIT();

    for (int kt = 0; kt < KT; kt++) {
        CP_WAIT(2);
        __syncthreads();
        if (kt + STAGES - 1 < KT)
            g1_load(tid, s_tok, e, bn0, dynb, kt + STAGES - 1, (kt + STAGES - 1) & 3);
        CP_COMMIT();
        compute_stage(c, fs, dynb + (kt & 3) * STAGE_BYTES);
    }
    __syncthreads();   // all warps done with stages before epilogue reuses smem

    // epilogue: gelu -> fp16 -> smem stage -> coalesced 16B stores
#pragma unroll
    for (int mf = 0; mf < 2; mf++)
#pragma unroll
        for (int nf = 0; nf < 8; nf++)
#pragma unroll
            for (int half = 0; half < 2; half++) {
                int row = mwarp * 32 + mf * 16 + (lane >> 2) + half * 8;
                int col = nwarp * 64 + nf * 8 + (lane & 3) * 2;
                float v0 = c[mf][nf][half * 2 + 0] + s_bias[col];
                float v1 = c[mf][nf][half * 2 + 1] + s_bias[col + 1];
                uint32_t off = (uint32_t)row * 256 + (((uint32_t)col * 2) ^ (((uint32_t)row & 15) << 4));
                *(uint32_t*)(dynp + off) =
                    packh(__float2half(gelu_exact(v0)), __float2half(gelu_exact(v1)));
            }
    __syncthreads();
#pragma unroll
    for (int it = 0; it < 8; it++) {
        int g = tid + it * 256;                  // 2048 16B chunks
        int r2 = g >> 4, seg = g & 15;
        uint32_t off = (uint32_t)r2 * 256 + (((uint32_t)seg * 16) ^ (((uint32_t)r2 & 15) << 4));
        uint4 vh = *(const uint4*)(dynp + off);
        size_t hb = ((size_t)(e * CAP + bm0 + r2)) * FDIM + bn0;
        *(uint4*)((char*)g_hh + hb * 2 + seg * 16) = vh;
    }
}

// ---------------- GEMM2: oute = (h @ W2 + b2) * vals ------------------------
__device__ __forceinline__ void g2_load(int tid, int e, int bn0, int bm0,
                                        uint32_t dynb, int kt, int st)
{
    int k0 = kt * BK;
    uint32_t base = dynb + st * STAGE_BYTES;
#pragma unroll
    for (int t = tid; t < 512; t += 256) {
        int row = t >> 2, cc = t & 3;
        uint32_t o = swz64((uint32_t)(row * 64 + cc * 16));
        size_t ga = (size_t)(e * CAP + bm0 + row) * FDIM + k0 + cc * 8;
        CP16(base + o, g_hh + ga);
        size_t gb = (size_t)(e * DDIM + bn0 + row) * FDIM + k0 + cc * 8;
        CP16(base + 8192 + o, g_w2h + gb);
    }
}

__global__ __launch_bounds__(256, 2) void k_gemm2_mma(const float* __restrict__ b2)
{
    extern __shared__ __align__(16) unsigned char dynraw[];
    __shared__ float s_val[BM];
    __shared__ float s_bias[BN];

    const int tid = threadIdx.x, wid = tid >> 5, lane = tid & 31;
    const int mwarp = wid & 3, nwarp = wid >> 2;
    const int e = blockIdx.z, bn0 = blockIdx.x * BN, bm0 = blockIdx.y * BM;

    uint32_t rawb = cvta_smem(dynraw);
    uint32_t pad = (1024u - (rawb & 1023u)) & 1023u;
    uint32_t dynb = rawb + pad;
    unsigned char* dynp = dynraw + pad;

    if (tid < BM) s_val[tid] = g_vals[e * CAP + bm0 + tid];
    if (tid < BN) s_bias[tid] = b2[e * DDIM + bn0 + tid];
    __syncthreads();

    FragState fs;
    frag_offsets(fs, lane, mwarp, nwarp);
    float c[2][8][4] = {};

    const int KT = FDIM / BK;  // 64
    g2_load(tid, e, bn0, bm0, dynb, 0, 0); CP_COMMIT();
    g2_load(tid, e, bn0, bm0, dynb, 1, 1); CP_COMMIT();
    g2_load(tid, e, bn0, bm0, dynb, 2, 2); CP_COMMIT();

    for (int kt = 0; kt < KT; kt++) {
        CP_WAIT(2);
        __syncthreads();
        if (kt + STAGES - 1 < KT)
            g2_load(tid, e, bn0, bm0, dynb, kt + STAGES - 1, (kt + STAGES - 1) & 3);
        CP_COMMIT();
        compute_stage(c, fs, dynb + (kt & 3) * STAGE_BYTES);
    }
    __syncthreads();

    // epilogue: (acc + b2) * val -> f32 smem stage (512B/row) -> 16B stores
#pragma unroll
    for (int mf = 0; mf < 2; mf++)
#pragma unroll
        for (int nf = 0; nf < 8; nf++)
#pragma unroll
            for (int half = 0; half < 2; half++) {
                int row = mwarp * 32 + mf * 16 + (lane >> 2) + half * 8;
                int col = nwarp * 64 + nf * 8 + (lane & 3) * 2;
                float vr = s_val[row];
                float2 o2;
                o2.x = (c[mf][nf][half * 2 + 0] + s_bias[col]) * vr;
                o2.y = (c[mf][nf][half * 2 + 1] + s_bias[col + 1]) * vr;
                uint32_t off = (uint32_t)row * 512 + (((uint32_t)col * 4) ^ (((uint32_t)row & 31) << 4));
                *(float2*)(dynp + off) = o2;
            }
    __syncthreads();
#pragma unroll
    for (int it = 0; it < 16; it++) {
        int g = tid + it * 256;                  // 4096 16B chunks
        int r2 = g >> 5, seg = g & 31;
        uint32_t off = (uint32_t)r2 * 512 + (((uint32_t)seg * 16) ^ (((uint32_t)r2 & 31) << 4));
        uint4 v = *(const uint4*)(dynp + off);
        size_t ob = ((size_t)(e * CAP + bm0 + r2)) * DDIM + bn0;
        *(uint4*)((char*)g_oute + ob * 4 + seg * 16) = v;
    }
}

// ---------------- K6: gather-reduce scatter to output -----------------------
__global__ void k_scatter(float* __restrict__ out)
{
    int t = blockIdx.x * 2 + (threadIdx.x >> 7);
    int l = threadIdx.x & 127;
    int cnt = g_tokcnt[t];
    float4 acc = make_float4(0.f, 0.f, 0.f, 0.f);
    for (int i = 0; i < cnt; i++) {
        int ref = g_toklist[t * 8 + i];
        float4 v = ((const float4*)(g_oute + (size_t)ref * DDIM))[l];
        acc.x += v.x; acc.y += v.y; acc.z += v.z; acc.w += v.w;
    }
    ((float4*)out)[(size_t)t * (DDIM / 4) + l] = acc;
}

// ---------------------------------------------------------------------------
extern "C" void kernel_launch(void* const* d_in, const int* in_sizes, int n_in,
                              void* d_out, int out_size)
{
    const float* x  = (const float*)d_in[0];
    const float* Wr = (const float*)d_in[1];
    const float* W1 = (const float*)d_in[2];
    const float* b1 = (const float*)d_in[3];
    const float* W2 = (const float*)d_in[4];
    const float* b2 = (const float*)d_in[5];
    float* out = (float*)d_out;

    cudaFuncSetAttribute(k_gemm1_mma, cudaFuncAttributeMaxDynamicSharedMemorySize, DYN_SMEM);
    cudaFuncSetAttribute(k_gemm2_mma, cudaFuncAttributeMaxDynamicSharedMemorySize, DYN_SMEM);

    k_cvt_x   <<<NTOK * DDIM / 1024, 256>>>((const float4*)x);
    k_cvt_w1  <<<dim3(FDIM / 32, DDIM / 32, NEXP), dim3(32, 8)>>>(W1);
    k_cvt_w2  <<<dim3(DDIM / 32, FDIM / 32, NEXP), dim3(32, 8)>>>(W2);
    k_logits  <<<NTOK / 8, 256>>>(x, Wr);
    k_colstats<<<NEXP, 512>>>();
    k_select  <<<NEXP, 1024>>>();
    k_gemm1_mma<<<dim3(FDIM / BN, CAP / BM, NEXP), 256, DYN_SMEM>>>(b1);
    k_gemm2_mma<<<dim3(DDIM / BN, CAP / BM, NEXP), 256, DYN_SMEM>>>(b2);
    k_scatter <<<NTOK / 2, 256>>>(out);
}